// round 2
// baseline (speedup 1.0000x reference)
#include <cuda_runtime.h>
#include <math.h>

#ifndef M_PI
#define M_PI 3.14159265358979323846
#endif

#define BATCH   256
#define T_LEN   65536
#define L_CHUNK 128
#define NC      (T_LEN / L_CHUNK)   // 512 chunks per batch row
#define LOG_NC  9                   // log2(NC)
#define NTOTAL  (BATCH * NC)        // 131072 chunk-threads

struct Coef { float b0, b1, b2, b3, b4, a1, a2, a3, a4; };
struct ScanArgs { float M[LOG_NC][16]; };   // (A^L)^(2^k), row-major 4x4

// Intermediates: end-states per chunk (pass1) and start-states (scan output).
__device__ float4 g_f[NTOTAL];
__device__ float4 g_s[NTOTAL];

// One DF2T step. 9 FMA-class ops.
__device__ __forceinline__ float iir_step(float xv, float& z0, float& z1,
                                          float& z2, float& z3, const Coef& c) {
    float y = fmaf(c.b0, xv, z0);
    z0 = fmaf(c.b1, xv, z1); z0 = fmaf(-c.a1, y, z0);
    z1 = fmaf(c.b2, xv, z2); z1 = fmaf(-c.a2, y, z1);
    z2 = fmaf(c.b3, xv, z3); z2 = fmaf(-c.a3, y, z2);
    z3 = c.b4 * xv;          z3 = fmaf(-c.a4, y, z3);
    return y;
}

// Pass 1: run each chunk from zero state, write only the final 4-float state.
__global__ void __launch_bounds__(256) pass1_kernel(const float* __restrict__ x, Coef cf) {
    int tid = blockIdx.x * 256 + threadIdx.x;
    int b = tid / NC;
    int c = tid % NC;
    const float4* xp = reinterpret_cast<const float4*>(
        x + (size_t)b * T_LEN + (size_t)c * L_CHUNK);
    float z0 = 0.f, z1 = 0.f, z2 = 0.f, z3 = 0.f;
#pragma unroll 4
    for (int i = 0; i < L_CHUNK / 4; i++) {
        float4 v = xp[i];
        iir_step(v.x, z0, z1, z2, z3, cf);
        iir_step(v.y, z0, z1, z2, z3, cf);
        iir_step(v.z, z0, z1, z2, z3, cf);
        iir_step(v.w, z0, z1, z2, z3, cf);
    }
    g_f[tid] = make_float4(z0, z1, z2, z3);
}

// Scan: per batch (block), Kogge-Stone inclusive scan over NC chunks with the
// affine operator v_c <- v_c + (A^L)^(2^k) * v_{c-2^k}. Then shift to exclusive.
__global__ void __launch_bounds__(NC) scan_kernel(ScanArgs sa) {
    __shared__ float4 sv[NC];
    int b = blockIdx.x;
    int c = threadIdx.x;
    float4 v = g_f[b * NC + c];
    sv[c] = v;
    __syncthreads();
#pragma unroll
    for (int k = 0; k < LOG_NC; k++) {
        int d = 1 << k;
        float4 p;
        bool has = (c >= d);
        if (has) p = sv[c - d];
        __syncthreads();
        if (has) {
            const float* M = sa.M[k];
            v.x += M[0]  * p.x + M[1]  * p.y + M[2]  * p.z + M[3]  * p.w;
            v.y += M[4]  * p.x + M[5]  * p.y + M[6]  * p.z + M[7]  * p.w;
            v.z += M[8]  * p.x + M[9]  * p.y + M[10] * p.z + M[11] * p.w;
            v.w += M[12] * p.x + M[13] * p.y + M[14] * p.z + M[15] * p.w;
            sv[c] = v;
        }
        __syncthreads();
    }
    float4 s0 = make_float4(0.f, 0.f, 0.f, 0.f);
    if (c > 0) s0 = sv[c - 1];
    g_s[b * NC + c] = s0;
}

// Pass 2: re-run each chunk seeded with the correct start state; write y.
__global__ void __launch_bounds__(256) pass2_kernel(const float* __restrict__ x,
                                                    float* __restrict__ yout, Coef cf) {
    int tid = blockIdx.x * 256 + threadIdx.x;
    int b = tid / NC;
    int c = tid % NC;
    size_t base = (size_t)b * T_LEN + (size_t)c * L_CHUNK;
    const float4* xp = reinterpret_cast<const float4*>(x + base);
    float4*       yp = reinterpret_cast<float4*>(yout + base);
    float4 s = g_s[tid];
    float z0 = s.x, z1 = s.y, z2 = s.z, z3 = s.w;
#pragma unroll 4
    for (int i = 0; i < L_CHUNK / 4; i++) {
        float4 v = xp[i];
        float4 o;
        o.x = iir_step(v.x, z0, z1, z2, z3, cf);
        o.y = iir_step(v.y, z0, z1, z2, z3, cf);
        o.z = iir_step(v.z, z0, z1, z2, z3, cf);
        o.w = iir_step(v.w, z0, z1, z2, z3, cf);
        yp[i] = o;
    }
}

// ---------------- host ----------------

struct Cd { double re, im; };
static inline Cd cadd(Cd a, Cd b) { return { a.re + b.re, a.im + b.im }; }
static inline Cd csub(Cd a, Cd b) { return { a.re - b.re, a.im - b.im }; }
static inline Cd cmul(Cd a, Cd b) {
    return { a.re * b.re - a.im * b.im, a.re * b.im + a.im * b.re };
}
static inline Cd cdiv(Cd a, Cd b) {
    double d = b.re * b.re + b.im * b.im;
    return { (a.re * b.re + a.im * b.im) / d, (a.im * b.re - a.re * b.im) / d };
}

static void matmul4(const double* A, const double* B, double* C) {
    for (int i = 0; i < 4; i++)
        for (int j = 0; j < 4; j++) {
            double s = 0.0;
            for (int k = 0; k < 4; k++) s += A[i * 4 + k] * B[k * 4 + j];
            C[i * 4 + j] = s;
        }
}

extern "C" void kernel_launch(void* const* d_in, const int* in_sizes, int n_in,
                              void* d_out, int out_size) {
    const float* x = (const float*)d_in[0];
    float* y = (float*)d_out;

    // ---- Butterworth design, exactly mirroring the reference numpy math ----
    const int ORDER = 4;
    const double WN = 4000.0 / (0.5 * 16000.0);   // 0.5
    const double fs2 = 4.0;
    double warped = fs2 * tan(M_PI * WN / 4.0);

    Cd p[4];
    for (int k = 1; k <= ORDER; k++) {
        double ang = M_PI * (2 * k + ORDER - 1) / (2.0 * ORDER);
        p[k - 1] = { warped * cos(ang), warped * sin(ang) };
    }
    double gain = warped * warped * warped * warped;

    Cd pd[4];
    Cd prodden = { 1.0, 0.0 };
    for (int i = 0; i < 4; i++) {
        Cd num = cadd({ fs2, 0.0 }, p[i]);
        Cd den = csub({ fs2, 0.0 }, p[i]);
        pd[i] = cdiv(num, den);
        prodden = cmul(prodden, den);
    }
    double kd = gain / prodden.re;
    // zeros all at z=-1: poly(-1,-1,-1,-1) = [1,4,6,4,1]
    double bcoef[5] = { kd, 4.0 * kd, 6.0 * kd, 4.0 * kd, kd };

    // acoef = real(poly(pd))
    Cd ac[5] = { {1,0}, {0,0}, {0,0}, {0,0}, {0,0} };
    for (int i = 0; i < 4; i++)
        for (int j = 4; j >= 1; j--)
            ac[j] = csub(ac[j], cmul(pd[i], ac[j - 1]));
    double acoef[5];
    for (int i = 0; i < 5; i++) acoef[i] = ac[i].re;

    // ---- state transition A (4x4): z_new = A z + Bv x  (DF2T, y eliminated) ----
    double A[16] = {0};
    for (int i = 0; i < 4; i++) {
        A[i * 4 + 0] -= acoef[i + 1];
        if (i < 3) A[i * 4 + (i + 1)] += 1.0;
    }

    // P = A^L_CHUNK by repeated squaring (L_CHUNK = 128 = 2^7)
    double P[16], Q[16];
    for (int i = 0; i < 16; i++) P[i] = A[i];
    for (int e = L_CHUNK; e > 1; e >>= 1) {
        matmul4(P, P, Q);
        for (int i = 0; i < 16; i++) P[i] = Q[i];
    }

    // ScanArgs: M[k] = (A^L)^(2^k)
    ScanArgs sa;
    for (int k = 0; k < LOG_NC; k++) {
        for (int i = 0; i < 16; i++) sa.M[k][i] = (float)P[i];
        matmul4(P, P, Q);
        for (int i = 0; i < 16; i++) P[i] = Q[i];
    }

    Coef cf;
    cf.b0 = (float)bcoef[0]; cf.b1 = (float)bcoef[1]; cf.b2 = (float)bcoef[2];
    cf.b3 = (float)bcoef[3]; cf.b4 = (float)bcoef[4];
    cf.a1 = (float)acoef[1]; cf.a2 = (float)acoef[2];
    cf.a3 = (float)acoef[3]; cf.a4 = (float)acoef[4];

    pass1_kernel<<<NTOTAL / 256, 256>>>(x, cf);
    scan_kernel<<<BATCH, NC>>>(sa);
    pass2_kernel<<<NTOTAL / 256, 256>>>(x, y, cf);
}

// round 3
// speedup vs baseline: 1.4631x; 1.4631x over previous
#include <cuda_runtime.h>
#include <math.h>

#ifndef M_PI
#define M_PI 3.14159265358979323846
#endif

#define BATCH     256
#define T_LEN     65536
#define L_CHUNK   128
#define NC        (T_LEN / L_CHUNK)       // 512 chunks per row
#define W_WARM    64                      // warmup overlap (0.758^64 ~ 2e-8)
#define CPB       128                     // chunks (= threads) per block
#define RB_PER_ROW (NC / CPB)             // 4 blocks per batch row
#define NBLK      (BATCH * RB_PER_ROW)    // 1024 blocks
#define REGION    (CPB * L_CHUNK)         // 16384 floats per block
#define PAD0      128                     // front pad (words) before region
#define DATA_WORDS (PAD0 + REGION)        // 16512
#define SMEM_BYTES ((DATA_WORDS + 4 * W_WARM) * 4)   // + weight table

struct Params {
    float b0, b1, b2, b3, b4;      // numerator
    float na1, na2, na3, na4;      // negated denominator taps
    float wq[4 * W_WARM];          // warmup weights, interleaved [j][4]
};

// Word-level swizzle: bijective (sources are higher/unmodified bits), keeps
// scalar chunk-strided accesses conflict-free and staging phases <=2-way.
__device__ __forceinline__ int swz(int idx) {
    return idx ^ ((idx >> 7) & 31) ^ ((idx >> 2) & 27);
}

__global__ void __launch_bounds__(CPB) fused_kernel(const float* __restrict__ x,
                                                    float* __restrict__ y,
                                                    Params P) {
    extern __shared__ float sm[];
    float* wsm = sm + DATA_WORDS;          // 256 warmup weights
    const int t   = threadIdx.x;
    const int blk = blockIdx.x;
    const int rb  = blk & (RB_PER_ROW - 1);
    const size_t gbase = (size_t)(blk >> 2) * T_LEN + (size_t)rb * REGION;

    // ---- stage: coalesced global float4 loads -> swizzled scalar STS ----
    const float4* xin = reinterpret_cast<const float4*>(x + gbase);
#pragma unroll
    for (int i = 0; i < REGION / (4 * CPB); i++) {     // 32 iters
        float4 d = xin[i * CPB + t];
        int idx = PAD0 + 4 * (i * CPB + t);
        sm[swz(idx + 0)] = d.x;
        sm[swz(idx + 1)] = d.y;
        sm[swz(idx + 2)] = d.z;
        sm[swz(idx + 3)] = d.w;
    }
    // front pad: 64 words at smem idx [64,128) = x[gbase-64 .. gbase)
    if (t < W_WARM / 4) {
        float4 d = make_float4(0.f, 0.f, 0.f, 0.f);
        if (rb != 0) d = reinterpret_cast<const float4*>(x + gbase - W_WARM)[t];
        int idx = PAD0 - W_WARM + 4 * t;
        sm[swz(idx + 0)] = d.x;
        sm[swz(idx + 1)] = d.y;
        sm[swz(idx + 2)] = d.z;
        sm[swz(idx + 3)] = d.w;
    }
    // warmup weights -> smem (broadcast-read later)
    for (int i = t; i < 4 * W_WARM; i += CPB) wsm[i] = P.wq[i];
    __syncthreads();

    // ---- warmup: state = sum_j A^(63-j) g * x_warm[j], 4 indep FMA chains ----
    float z0 = 0.f, z1 = 0.f, z2 = 0.f, z3 = 0.f;
    if (rb != 0 || t != 0) {                 // first chunk of a row: exact zero state
        const int wb = PAD0 - W_WARM + 128 * t;   // idx of warmup window start
#pragma unroll
        for (int j = 0; j < W_WARM; j++) {
            float xv = sm[swz(wb + j)];
            float4 w = reinterpret_cast<const float4*>(wsm)[j];
            z0 = fmaf(w.x, xv, z0);
            z1 = fmaf(w.y, xv, z1);
            z2 = fmaf(w.z, xv, z2);
            z3 = fmaf(w.w, xv, z3);
        }
    }
    __syncthreads();   // others read my chunk tail (warmup) before I overwrite it

    // ---- main: DF2T over own chunk, y written back in place ----
    {
        const int base = PAD0 + 128 * t;
#pragma unroll 32
        for (int j = 0; j < L_CHUNK; j++) {
            int a = swz(base + j);
            float xv = sm[a];
            float yv = fmaf(P.b0, xv, z0);
            z0 = fmaf(P.b1, xv, z1); z0 = fmaf(P.na1, yv, z0);
            z1 = fmaf(P.b2, xv, z2); z1 = fmaf(P.na2, yv, z1);
            z2 = fmaf(P.b3, xv, z3); z2 = fmaf(P.na3, yv, z2);
            z3 = P.b4 * xv;          z3 = fmaf(P.na4, yv, z3);
            sm[a] = yv;
        }
    }
    __syncthreads();

    // ---- store: swizzled scalar LDS -> coalesced global float4 stores ----
    float4* yout = reinterpret_cast<float4*>(y + gbase);
#pragma unroll
    for (int i = 0; i < REGION / (4 * CPB); i++) {
        int idx = PAD0 + 4 * (i * CPB + t);
        float4 d;
        d.x = sm[swz(idx + 0)];
        d.y = sm[swz(idx + 1)];
        d.z = sm[swz(idx + 2)];
        d.w = sm[swz(idx + 3)];
        yout[i * CPB + t] = d;
    }
}

// ---------------- host ----------------

struct Cd { double re, im; };
static inline Cd cadd(Cd a, Cd b) { return { a.re + b.re, a.im + b.im }; }
static inline Cd csub(Cd a, Cd b) { return { a.re - b.re, a.im - b.im }; }
static inline Cd cmul(Cd a, Cd b) {
    return { a.re * b.re - a.im * b.im, a.re * b.im + a.im * b.re };
}
static inline Cd cdiv(Cd a, Cd b) {
    double d = b.re * b.re + b.im * b.im;
    return { (a.re * b.re + a.im * b.im) / d, (a.im * b.re - a.re * b.im) / d };
}

extern "C" void kernel_launch(void* const* d_in, const int* in_sizes, int n_in,
                              void* d_out, int out_size) {
    const float* x = (const float*)d_in[0];
    float* y = (float*)d_out;

    // ---- Butterworth design, exactly mirroring the reference numpy math ----
    const int ORDER = 4;
    const double WN = 4000.0 / (0.5 * 16000.0);   // 0.5
    const double fs2 = 4.0;
    double warped = fs2 * tan(M_PI * WN / 4.0);

    Cd p[4];
    for (int k = 1; k <= ORDER; k++) {
        double ang = M_PI * (2 * k + ORDER - 1) / (2.0 * ORDER);
        p[k - 1] = { warped * cos(ang), warped * sin(ang) };
    }
    double gain = warped * warped * warped * warped;

    Cd pd[4];
    Cd prodden = { 1.0, 0.0 };
    for (int i = 0; i < 4; i++) {
        Cd num = cadd({ fs2, 0.0 }, p[i]);
        Cd den = csub({ fs2, 0.0 }, p[i]);
        pd[i] = cdiv(num, den);
        prodden = cmul(prodden, den);
    }
    double kd = gain / prodden.re;
    double bcoef[5] = { kd, 4.0 * kd, 6.0 * kd, 4.0 * kd, kd };

    Cd ac[5] = { {1,0}, {0,0}, {0,0}, {0,0}, {0,0} };
    for (int i = 0; i < 4; i++)
        for (int j = 4; j >= 1; j--)
            ac[j] = csub(ac[j], cmul(pd[i], ac[j - 1]));
    double acoef[5];
    for (int i = 0; i < 5; i++) acoef[i] = ac[i].re;

    // state transition: z' = A z + g x  (DF2T with y eliminated)
    double A[16] = {0};
    for (int i = 0; i < 4; i++) {
        A[i * 4 + 0] -= acoef[i + 1];
        if (i < 3) A[i * 4 + (i + 1)] += 1.0;
    }
    double g[4];
    for (int i = 0; i < 4; i++) g[i] = bcoef[i + 1] - acoef[i + 1] * bcoef[0];

    Params P;
    P.b0 = (float)bcoef[0]; P.b1 = (float)bcoef[1]; P.b2 = (float)bcoef[2];
    P.b3 = (float)bcoef[3]; P.b4 = (float)bcoef[4];
    P.na1 = (float)(-acoef[1]); P.na2 = (float)(-acoef[2]);
    P.na3 = (float)(-acoef[3]); P.na4 = (float)(-acoef[4]);

    // warmup weights: w_j = A^(W-1-j) g  (oldest sample gets highest power)
    double wv[4] = { g[0], g[1], g[2], g[3] };
    for (int j = W_WARM - 1; j >= 0; j--) {
        for (int k = 0; k < 4; k++) P.wq[4 * j + k] = (float)wv[k];
        double nv[4];
        for (int i = 0; i < 4; i++) {
            nv[i] = 0.0;
            for (int k2 = 0; k2 < 4; k2++) nv[i] += A[i * 4 + k2] * wv[k2];
        }
        for (int i = 0; i < 4; i++) wv[i] = nv[i];
    }

    cudaFuncSetAttribute(fused_kernel, cudaFuncAttributeMaxDynamicSharedMemorySize,
                         SMEM_BYTES);
    fused_kernel<<<NBLK, CPB, SMEM_BYTES>>>(x, y, P);
}

// round 5
// speedup vs baseline: 1.7123x; 1.1704x over previous
#include <cuda_runtime.h>
#include <math.h>

#ifndef M_PI
#define M_PI 3.14159265358979323846
#endif

#define BATCH      256
#define T_LEN      65536
#define L_CHUNK    64
#define W_WARM     48                      // |p|^48 ~ 1.7e-6
#define CPB        128                     // chunks (= threads) per block
#define REGION     (CPB * L_CHUNK)         // 8192 floats = 32KB
#define RB_PER_ROW (T_LEN / REGION)        // 8 blocks per batch row
#define NBLK       (BATCH * RB_PER_ROW)    // 2048 blocks

struct Params {
    float b0, b1, b2, b3, b4;      // numerator
    float na1, na2, na3, na4;      // negated denominator taps
    float wq[4 * W_WARM];          // warmup weights, interleaved [j][4]
};

// Transposed layout: word (chunk c, sample j) lives at j*CPB + (c ^ (j&31)).
// - compute phase: j fixed across warp, c = lane  -> banks (c^k)&31 distinct
// - staging/output: c fixed per warp, j&31 = lane -> banks (c^l)&31 distinct
__device__ __forceinline__ int sidx(int c, int j) {
    return j * CPB + (c ^ (j & 31));
}

__global__ void __launch_bounds__(CPB, 6) fused_kernel(const float* __restrict__ x,
                                                       float* __restrict__ y,
                                                       Params P) {
    __shared__ float  sm[REGION];
    __shared__ float  padx[W_WARM];
    __shared__ float4 wsm[W_WARM];

    const int t   = threadIdx.x;
    const int blk = blockIdx.x;
    const int rb  = blk & (RB_PER_ROW - 1);
    const size_t gbase = (size_t)(blk >> 3) * T_LEN + (size_t)rb * REGION;

    // ---- stage: coalesced scalar loads -> conflict-free transposed STS ----
#pragma unroll
    for (int i = 0; i < REGION / CPB; i++) {     // 64 iters
        int widx = i * CPB + t;
        sm[sidx(widx >> 6, widx & 63)] = x[gbase + widx];
    }
    if (t < W_WARM) {
        padx[t] = (rb != 0) ? x[gbase - W_WARM + t] : 0.f;
        wsm[t] = make_float4(P.wq[4 * t + 0], P.wq[4 * t + 1],
                             P.wq[4 * t + 2], P.wq[4 * t + 3]);
    }
    __syncthreads();

    // ---- warmup: state = sum_j A^(W-1-j) g * x_prev[j]  (4 indep chains) ----
    float z0 = 0.f, z1 = 0.f, z2 = 0.f, z3 = 0.f;
    if (t == 0) {
        if (rb != 0) {
#pragma unroll
            for (int j = 0; j < W_WARM; j++) {
                float xv = padx[j];
                float4 w = wsm[j];
                z0 = fmaf(w.x, xv, z0);
                z1 = fmaf(w.y, xv, z1);
                z2 = fmaf(w.z, xv, z2);
                z3 = fmaf(w.w, xv, z3);
            }
        }
    } else {
        const int c = t - 1;                       // tail of previous chunk
#pragma unroll
        for (int jj = 0; jj < W_WARM; jj++) {
            float xv = sm[sidx(c, (L_CHUNK - W_WARM) + jj)];
            float4 w = wsm[jj];
            z0 = fmaf(w.x, xv, z0);
            z1 = fmaf(w.y, xv, z1);
            z2 = fmaf(w.z, xv, z2);
            z3 = fmaf(w.w, xv, z3);
        }
    }
    __syncthreads();   // all warmup reads done before in-place overwrite

    // ---- main: DF2T over own chunk, y written back in place ----
#pragma unroll
    for (int j = 0; j < L_CHUNK; j++) {
        int a = sidx(t, j);                        // base_j + (t ^ const_j)
        float xv = sm[a];
        float yv = fmaf(P.b0, xv, z0);
        z0 = fmaf(P.b1, xv, z1); z0 = fmaf(P.na1, yv, z0);
        z1 = fmaf(P.b2, xv, z2); z1 = fmaf(P.na2, yv, z1);
        z2 = fmaf(P.b3, xv, z3); z2 = fmaf(P.na3, yv, z2);
        z3 = P.b4 * xv;          z3 = fmaf(P.na4, yv, z3);
        sm[a] = yv;
    }
    __syncthreads();

    // ---- output: conflict-free transposed LDS -> coalesced scalar stores ----
#pragma unroll
    for (int i = 0; i < REGION / CPB; i++) {
        int widx = i * CPB + t;
        y[gbase + widx] = sm[sidx(widx >> 6, widx & 63)];
    }
}

// ---------------- host ----------------

struct Cd { double re, im; };
static inline Cd cadd(Cd a, Cd b) { return { a.re + b.re, a.im + b.im }; }
static inline Cd csub(Cd a, Cd b) { return { a.re - b.re, a.im - b.im }; }
static inline Cd cmul(Cd a, Cd b) {
    return { a.re * b.re - a.im * b.im, a.re * b.im + a.im * b.re };
}
static inline Cd cdiv(Cd a, Cd b) {
    double d = b.re * b.re + b.im * b.im;
    return { (a.re * b.re + a.im * b.im) / d, (a.im * b.re - a.re * b.im) / d };
}

extern "C" void kernel_launch(void* const* d_in, const int* in_sizes, int n_in,
                              void* d_out, int out_size) {
    const float* x = (const float*)d_in[0];
    float* y = (float*)d_out;

    // ---- Butterworth design, exactly mirroring the reference numpy math ----
    const int ORDER = 4;
    const double WN = 4000.0 / (0.5 * 16000.0);   // 0.5
    const double fs2 = 4.0;
    double warped = fs2 * tan(M_PI * WN / 4.0);

    Cd p[4];
    for (int k = 1; k <= ORDER; k++) {
        double ang = M_PI * (2 * k + ORDER - 1) / (2.0 * ORDER);
        p[k - 1] = { warped * cos(ang), warped * sin(ang) };
    }
    double gain = warped * warped * warped * warped;

    Cd pd[4];
    Cd prodden = { 1.0, 0.0 };
    for (int i = 0; i < 4; i++) {
        Cd num = cadd({ fs2, 0.0 }, p[i]);
        Cd den = csub({ fs2, 0.0 }, p[i]);
        pd[i] = cdiv(num, den);
        prodden = cmul(prodden, den);
    }
    double kd = gain / prodden.re;
    double bcoef[5] = { kd, 4.0 * kd, 6.0 * kd, 4.0 * kd, kd };

    Cd ac[5] = { {1,0}, {0,0}, {0,0}, {0,0}, {0,0} };
    for (int i = 0; i < 4; i++)
        for (int j = 4; j >= 1; j--)
            ac[j] = csub(ac[j], cmul(pd[i], ac[j - 1]));
    double acoef[5];
    for (int i = 0; i < 5; i++) acoef[i] = ac[i].re;

    // state transition: z' = A z + g x  (DF2T with y eliminated)
    double A[16] = {0};
    for (int i = 0; i < 4; i++) {
        A[i * 4 + 0] -= acoef[i + 1];
        if (i < 3) A[i * 4 + (i + 1)] += 1.0;
    }
    double g[4];
    for (int i = 0; i < 4; i++) g[i] = bcoef[i + 1] - acoef[i + 1] * bcoef[0];

    Params P;
    P.b0 = (float)bcoef[0]; P.b1 = (float)bcoef[1]; P.b2 = (float)bcoef[2];
    P.b3 = (float)bcoef[3]; P.b4 = (float)bcoef[4];
    P.na1 = (float)(-acoef[1]); P.na2 = (float)(-acoef[2]);
    P.na3 = (float)(-acoef[3]); P.na4 = (float)(-acoef[4]);

    // warmup weights: w_j = A^(W-1-j) g  (oldest sample gets highest power)
    double wv[4] = { g[0], g[1], g[2], g[3] };
    for (int j = W_WARM - 1; j >= 0; j--) {
        for (int k = 0; k < 4; k++) P.wq[4 * j + k] = (float)wv[k];
        double nv[4];
        for (int i = 0; i < 4; i++) {
            nv[i] = 0.0;
            for (int k2 = 0; k2 < 4; k2++) nv[i] += A[i * 4 + k2] * wv[k2];
        }
        for (int i = 0; i < 4; i++) wv[i] = nv[i];
    }

    fused_kernel<<<NBLK, CPB>>>(x, y, P);
}

// round 7
// speedup vs baseline: 2.3585x; 1.3774x over previous
#include <cuda_runtime.h>
#include <math.h>

#ifndef M_PI
#define M_PI 3.14159265358979323846
#endif

#define BATCH      256
#define T_LEN      65536
#define L_CHUNK    64
#define W_WARM     48                      // |p|^48 ~ 1.7e-6
#define CPB        128                     // chunks (= threads) per block
#define REGION     (CPB * L_CHUNK)         // 8192 floats = 32KB
#define RB_PER_ROW (T_LEN / REGION)        // 8 blocks per batch row
#define NBLK       (BATCH * RB_PER_ROW)    // 2048 blocks

struct Params {
    float b0, b1, b2, b3, b4;      // numerator
    float na1, na2, na3, na4;      // negated denominator taps
    float wq[4 * W_WARM];          // warmup weights, interleaved [j][4]
};

// 16B-granule swizzle: word (chunk c, sample j) -> c*64 + (j ^ ((c&7)<<2)).
// XOR touches only bits 2..4, so aligned float4 groups stay contiguous:
// every phase of every 128-bit smem op below is bank-conflict-free.
__device__ __forceinline__ int sidx4(int c, int j) {
    return c * L_CHUNK + (j ^ ((c & 7) << 2));
}

__device__ __forceinline__ void cpa16(unsigned dst_smem, const void* src) {
    asm volatile("cp.async.cg.shared.global [%0], [%1], 16;\n"
                 :: "r"(dst_smem), "l"(src));
}

__global__ void __launch_bounds__(CPB, 6) fused_kernel(const float* __restrict__ x,
                                                       float* __restrict__ y,
                                                       Params P) {
    __shared__ float4 smv[REGION / 4];
    __shared__ float4 padx4[W_WARM / 4];
    __shared__ float4 wsm[W_WARM];
    float* sm = reinterpret_cast<float*>(smv);

    const int t   = threadIdx.x;
    const int blk = blockIdx.x;
    const int rb  = blk & (RB_PER_ROW - 1);
    const size_t gbase = (size_t)(blk >> 3) * T_LEN + (size_t)rb * REGION;

    // ---- stage: coalesced 16B cp.async -> swizzled smem ----
    const float4* xin = reinterpret_cast<const float4*>(x + gbase);
    unsigned smb = (unsigned)__cvta_generic_to_shared(sm);
#pragma unroll
    for (int i = 0; i < REGION / (4 * CPB); i++) {   // 16 iters
        int vidx = i * CPB + t;
        int c = vidx >> 4;                // 16 float4 per chunk
        int j = (vidx & 15) * 4;
        cpa16(smb + sidx4(c, j) * 4u, xin + vidx);
    }
    if (t < W_WARM / 4) {
        float4 d = make_float4(0.f, 0.f, 0.f, 0.f);
        if (rb != 0)
            d = reinterpret_cast<const float4*>(x + gbase - W_WARM)[t];
        padx4[t] = d;
    }
    if (t < W_WARM)
        wsm[t] = make_float4(P.wq[4 * t + 0], P.wq[4 * t + 1],
                             P.wq[4 * t + 2], P.wq[4 * t + 3]);
    asm volatile("cp.async.commit_group;\n");
    asm volatile("cp.async.wait_group 0;\n");
    __syncthreads();

    // ---- warmup: state = sum_j A^(W-1-j) g * x_prev[j]  (4 indep chains) ----
    float z0 = 0.f, z1 = 0.f, z2 = 0.f, z3 = 0.f;
    if (t == 0) {
        if (rb != 0) {
#pragma unroll
            for (int q = 0; q < W_WARM / 4; q++) {
                float4 xv = padx4[q];
                float4 w0 = wsm[4 * q + 0], w1 = wsm[4 * q + 1];
                float4 w2 = wsm[4 * q + 2], w3 = wsm[4 * q + 3];
                z0 = fmaf(w0.x, xv.x, z0); z1 = fmaf(w0.y, xv.x, z1);
                z2 = fmaf(w0.z, xv.x, z2); z3 = fmaf(w0.w, xv.x, z3);
                z0 = fmaf(w1.x, xv.y, z0); z1 = fmaf(w1.y, xv.y, z1);
                z2 = fmaf(w1.z, xv.y, z2); z3 = fmaf(w1.w, xv.y, z3);
                z0 = fmaf(w2.x, xv.z, z0); z1 = fmaf(w2.y, xv.z, z1);
                z2 = fmaf(w2.z, xv.z, z2); z3 = fmaf(w2.w, xv.z, z3);
                z0 = fmaf(w3.x, xv.w, z0); z1 = fmaf(w3.y, xv.w, z1);
                z2 = fmaf(w3.z, xv.w, z2); z3 = fmaf(w3.w, xv.w, z3);
            }
        }
    } else {
        const int c = t - 1;                         // tail of previous chunk
#pragma unroll
        for (int q = 0; q < W_WARM / 4; q++) {
            float4 xv = *reinterpret_cast<const float4*>(
                &sm[sidx4(c, (L_CHUNK - W_WARM) + 4 * q)]);
            float4 w0 = wsm[4 * q + 0], w1 = wsm[4 * q + 1];
            float4 w2 = wsm[4 * q + 2], w3 = wsm[4 * q + 3];
            z0 = fmaf(w0.x, xv.x, z0); z1 = fmaf(w0.y, xv.x, z1);
            z2 = fmaf(w0.z, xv.x, z2); z3 = fmaf(w0.w, xv.x, z3);
            z0 = fmaf(w1.x, xv.y, z0); z1 = fmaf(w1.y, xv.y, z1);
            z2 = fmaf(w1.z, xv.y, z2); z3 = fmaf(w1.w, xv.y, z3);
            z0 = fmaf(w2.x, xv.z, z0); z1 = fmaf(w2.y, xv.z, z1);
            z2 = fmaf(w2.z, xv.z, z2); z3 = fmaf(w2.w, xv.z, z3);
            z0 = fmaf(w3.x, xv.w, z0); z1 = fmaf(w3.y, xv.w, z1);
            z2 = fmaf(w3.z, xv.w, z2); z3 = fmaf(w3.w, xv.w, z3);
        }
    }
    __syncthreads();   // all warmup reads done before in-place overwrite

    // ---- main: DF2T over own chunk (vectorized smem IO), y in place ----
#pragma unroll
    for (int q = 0; q < L_CHUNK / 4; q++) {
        float4* ap = reinterpret_cast<float4*>(&sm[sidx4(t, 4 * q)]);
        float4 xv = *ap;
        float4 ov;
        {   float xvv = xv.x;
            float yv = fmaf(P.b0, xvv, z0);
            z0 = fmaf(P.b1, xvv, z1); z0 = fmaf(P.na1, yv, z0);
            z1 = fmaf(P.b2, xvv, z2); z1 = fmaf(P.na2, yv, z1);
            z2 = fmaf(P.b3, xvv, z3); z2 = fmaf(P.na3, yv, z2);
            z3 = P.b4 * xvv;          z3 = fmaf(P.na4, yv, z3);
            ov.x = yv; }
        {   float xvv = xv.y;
            float yv = fmaf(P.b0, xvv, z0);
            z0 = fmaf(P.b1, xvv, z1); z0 = fmaf(P.na1, yv, z0);
            z1 = fmaf(P.b2, xvv, z2); z1 = fmaf(P.na2, yv, z1);
            z2 = fmaf(P.b3, xvv, z3); z2 = fmaf(P.na3, yv, z2);
            z3 = P.b4 * xvv;          z3 = fmaf(P.na4, yv, z3);
            ov.y = yv; }
        {   float xvv = xv.z;
            float yv = fmaf(P.b0, xvv, z0);
            z0 = fmaf(P.b1, xvv, z1); z0 = fmaf(P.na1, yv, z0);
            z1 = fmaf(P.b2, xvv, z2); z1 = fmaf(P.na2, yv, z1);
            z2 = fmaf(P.b3, xvv, z3); z2 = fmaf(P.na3, yv, z2);
            z3 = P.b4 * xvv;          z3 = fmaf(P.na4, yv, z3);
            ov.z = yv; }
        {   float xvv = xv.w;
            float yv = fmaf(P.b0, xvv, z0);
            z0 = fmaf(P.b1, xvv, z1); z0 = fmaf(P.na1, yv, z0);
            z1 = fmaf(P.b2, xvv, z2); z1 = fmaf(P.na2, yv, z1);
            z2 = fmaf(P.b3, xvv, z3); z2 = fmaf(P.na3, yv, z2);
            z3 = P.b4 * xvv;          z3 = fmaf(P.na4, yv, z3);
            ov.w = yv; }
        *ap = ov;
    }
    __syncthreads();

    // ---- output: swizzled LDS.128 -> coalesced STG.128 ----
    float4* yout = reinterpret_cast<float4*>(y + gbase);
#pragma unroll
    for (int i = 0; i < REGION / (4 * CPB); i++) {
        int vidx = i * CPB + t;
        int c = vidx >> 4;
        int j = (vidx & 15) * 4;
        yout[vidx] = *reinterpret_cast<const float4*>(&sm[sidx4(c, j)]);
    }
}

// ---------------- host ----------------

struct Cd { double re, im; };
static inline Cd cadd(Cd a, Cd b) { return { a.re + b.re, a.im + b.im }; }
static inline Cd csub(Cd a, Cd b) { return { a.re - b.re, a.im - b.im }; }
static inline Cd cmul(Cd a, Cd b) {
    return { a.re * b.re - a.im * b.im, a.re * b.im + a.im * b.re };
}
static inline Cd cdiv(Cd a, Cd b) {
    double d = b.re * b.re + b.im * b.im;
    return { (a.re * b.re + a.im * b.im) / d, (a.im * b.re - a.re * b.im) / d };
}

extern "C" void kernel_launch(void* const* d_in, const int* in_sizes, int n_in,
                              void* d_out, int out_size) {
    const float* x = (const float*)d_in[0];
    float* y = (float*)d_out;

    // ---- Butterworth design, exactly mirroring the reference numpy math ----
    const int ORDER = 4;
    const double WN = 4000.0 / (0.5 * 16000.0);   // 0.5
    const double fs2 = 4.0;
    double warped = fs2 * tan(M_PI * WN / 4.0);

    Cd p[4];
    for (int k = 1; k <= ORDER; k++) {
        double ang = M_PI * (2 * k + ORDER - 1) / (2.0 * ORDER);
        p[k - 1] = { warped * cos(ang), warped * sin(ang) };
    }
    double gain = warped * warped * warped * warped;

    Cd pd[4];
    Cd prodden = { 1.0, 0.0 };
    for (int i = 0; i < 4; i++) {
        Cd num = cadd({ fs2, 0.0 }, p[i]);
        Cd den = csub({ fs2, 0.0 }, p[i]);
        pd[i] = cdiv(num, den);
        prodden = cmul(prodden, den);
    }
    double kd = gain / prodden.re;
    double bcoef[5] = { kd, 4.0 * kd, 6.0 * kd, 4.0 * kd, kd };

    Cd ac[5] = { {1,0}, {0,0}, {0,0}, {0,0}, {0,0} };
    for (int i = 0; i < 4; i++)
        for (int j = 4; j >= 1; j--)
            ac[j] = csub(ac[j], cmul(pd[i], ac[j - 1]));
    double acoef[5];
    for (int i = 0; i < 5; i++) acoef[i] = ac[i].re;

    // state transition: z' = A z + g x  (DF2T with y eliminated)
    double A[16] = {0};
    for (int i = 0; i < 4; i++) {
        A[i * 4 + 0] -= acoef[i + 1];
        if (i < 3) A[i * 4 + (i + 1)] += 1.0;
    }
    double g[4];
    for (int i = 0; i < 4; i++) g[i] = bcoef[i + 1] - acoef[i + 1] * bcoef[0];

    Params P;
    P.b0 = (float)bcoef[0]; P.b1 = (float)bcoef[1]; P.b2 = (float)bcoef[2];
    P.b3 = (float)bcoef[3]; P.b4 = (float)bcoef[4];
    P.na1 = (float)(-acoef[1]); P.na2 = (float)(-acoef[2]);
    P.na3 = (float)(-acoef[3]); P.na4 = (float)(-acoef[4]);

    // warmup weights: w_j = A^(W-1-j) g  (oldest sample gets highest power)
    double wv[4] = { g[0], g[1], g[2], g[3] };
    for (int j = W_WARM - 1; j >= 0; j--) {
        for (int k = 0; k < 4; k++) P.wq[4 * j + k] = (float)wv[k];
        double nv[4];
        for (int i = 0; i < 4; i++) {
            nv[i] = 0.0;
            for (int k2 = 0; k2 < 4; k2++) nv[i] += A[i * 4 + k2] * wv[k2];
        }
        for (int i = 0; i < 4; i++) wv[i] = nv[i];
    }

    fused_kernel<<<NBLK, CPB>>>(x, y, P);
}

// round 8
// speedup vs baseline: 2.5543x; 1.0830x over previous
#include <cuda_runtime.h>
#include <math.h>

#ifndef M_PI
#define M_PI 3.14159265358979323846
#endif

#define BATCH      256
#define T_LEN      65536
#define L_CHUNK    64
#define W_WARM     48                      // |p|^48 ~ 1.7e-6
#define CPB        128                     // chunks (= threads) per block
#define REGION     (CPB * L_CHUNK)         // 8192 floats = 32KB
#define RB_PER_ROW (T_LEN / REGION)        // 8 blocks per batch row
#define NBLK       (BATCH * RB_PER_ROW)    // 2048 blocks

struct Params {
    float b0, b1, b2, b3, b4;      // numerator
    float na1, na2, na3, na4;      // negated denominator taps
    float4 wq4[W_WARM];            // warmup weights w_j = A^(W-1-j) g (const space)
};

// 16B-granule swizzle: word (chunk c, sample j) -> c*64 + (j ^ ((c&7)<<2)).
// XOR touches only bits 2..4, so aligned float4 groups stay contiguous:
// every phase of every 128-bit smem op below is bank-conflict-free.
__device__ __forceinline__ int sidx4(int c, int j) {
    return c * L_CHUNK + (j ^ ((c & 7) << 2));
}

__device__ __forceinline__ void cpa16(unsigned dst_smem, const void* src) {
    asm volatile("cp.async.cg.shared.global [%0], [%1], 16;\n"
                 :: "r"(dst_smem), "l"(src));
}

__global__ void __launch_bounds__(CPB, 7) fused_kernel(const float* __restrict__ x,
                                                       float* __restrict__ y,
                                                       Params P) {
    __shared__ float4 smv[REGION / 4];
    __shared__ float4 padx4[W_WARM / 4];
    float* sm = reinterpret_cast<float*>(smv);

    const int t   = threadIdx.x;
    const int blk = blockIdx.x;
    const int rb  = blk & (RB_PER_ROW - 1);
    const size_t gbase = (size_t)(blk >> 3) * T_LEN + (size_t)rb * REGION;

    // ---- stage: coalesced 16B cp.async -> swizzled smem ----
    const float4* xin = reinterpret_cast<const float4*>(x + gbase);
    unsigned smb = (unsigned)__cvta_generic_to_shared(sm);
#pragma unroll
    for (int i = 0; i < REGION / (4 * CPB); i++) {   // 16 iters
        int vidx = i * CPB + t;
        int c = vidx >> 4;                // 16 float4 per chunk
        int j = (vidx & 15) * 4;
        cpa16(smb + sidx4(c, j) * 4u, xin + vidx);
    }
    if (t < W_WARM / 4) {
        float4 d = make_float4(0.f, 0.f, 0.f, 0.f);
        if (rb != 0)
            d = reinterpret_cast<const float4*>(x + gbase - W_WARM)[t];
        padx4[t] = d;
    }
    asm volatile("cp.async.commit_group;\n");
    asm volatile("cp.async.wait_group 0;\n");
    __syncthreads();

    // ---- warmup: state = sum_j A^(W-1-j) g * x_prev[j]  (4 indep chains) ----
    // Weights come straight from the constant bank (uniform LDCU, no smem).
    float z0 = 0.f, z1 = 0.f, z2 = 0.f, z3 = 0.f;
    if (t == 0) {
        if (rb != 0) {
#pragma unroll
            for (int q = 0; q < W_WARM / 4; q++) {
                float4 xv = padx4[q];
                float4 w0 = P.wq4[4 * q + 0], w1 = P.wq4[4 * q + 1];
                float4 w2 = P.wq4[4 * q + 2], w3 = P.wq4[4 * q + 3];
                z0 = fmaf(w0.x, xv.x, z0); z1 = fmaf(w0.y, xv.x, z1);
                z2 = fmaf(w0.z, xv.x, z2); z3 = fmaf(w0.w, xv.x, z3);
                z0 = fmaf(w1.x, xv.y, z0); z1 = fmaf(w1.y, xv.y, z1);
                z2 = fmaf(w1.z, xv.y, z2); z3 = fmaf(w1.w, xv.y, z3);
                z0 = fmaf(w2.x, xv.z, z0); z1 = fmaf(w2.y, xv.z, z1);
                z2 = fmaf(w2.z, xv.z, z2); z3 = fmaf(w2.w, xv.z, z3);
                z0 = fmaf(w3.x, xv.w, z0); z1 = fmaf(w3.y, xv.w, z1);
                z2 = fmaf(w3.z, xv.w, z2); z3 = fmaf(w3.w, xv.w, z3);
            }
        }
    } else {
        const int c = t - 1;                         // tail of previous chunk
#pragma unroll
        for (int q = 0; q < W_WARM / 4; q++) {
            float4 xv = *reinterpret_cast<const float4*>(
                &sm[sidx4(c, (L_CHUNK - W_WARM) + 4 * q)]);
            float4 w0 = P.wq4[4 * q + 0], w1 = P.wq4[4 * q + 1];
            float4 w2 = P.wq4[4 * q + 2], w3 = P.wq4[4 * q + 3];
            z0 = fmaf(w0.x, xv.x, z0); z1 = fmaf(w0.y, xv.x, z1);
            z2 = fmaf(w0.z, xv.x, z2); z3 = fmaf(w0.w, xv.x, z3);
            z0 = fmaf(w1.x, xv.y, z0); z1 = fmaf(w1.y, xv.y, z1);
            z2 = fmaf(w1.z, xv.y, z2); z3 = fmaf(w1.w, xv.y, z3);
            z0 = fmaf(w2.x, xv.z, z0); z1 = fmaf(w2.y, xv.z, z1);
            z2 = fmaf(w2.z, xv.z, z2); z3 = fmaf(w2.w, xv.z, z3);
            z0 = fmaf(w3.x, xv.w, z0); z1 = fmaf(w3.y, xv.w, z1);
            z2 = fmaf(w3.z, xv.w, z2); z3 = fmaf(w3.w, xv.w, z3);
        }
    }
    __syncthreads();   // all warmup reads done before in-place overwrite

    // ---- main: DF2T over own chunk (vectorized smem IO), y in place ----
#pragma unroll
    for (int q = 0; q < L_CHUNK / 4; q++) {
        float4* ap = reinterpret_cast<float4*>(&sm[sidx4(t, 4 * q)]);
        float4 xv = *ap;
        float4 ov;
        {   float xvv = xv.x;
            float yv = fmaf(P.b0, xvv, z0);
            z0 = fmaf(P.b1, xvv, z1); z0 = fmaf(P.na1, yv, z0);
            z1 = fmaf(P.b2, xvv, z2); z1 = fmaf(P.na2, yv, z1);
            z2 = fmaf(P.b3, xvv, z3); z2 = fmaf(P.na3, yv, z2);
            z3 = P.b4 * xvv;          z3 = fmaf(P.na4, yv, z3);
            ov.x = yv; }
        {   float xvv = xv.y;
            float yv = fmaf(P.b0, xvv, z0);
            z0 = fmaf(P.b1, xvv, z1); z0 = fmaf(P.na1, yv, z0);
            z1 = fmaf(P.b2, xvv, z2); z1 = fmaf(P.na2, yv, z1);
            z2 = fmaf(P.b3, xvv, z3); z2 = fmaf(P.na3, yv, z2);
            z3 = P.b4 * xvv;          z3 = fmaf(P.na4, yv, z3);
            ov.y = yv; }
        {   float xvv = xv.z;
            float yv = fmaf(P.b0, xvv, z0);
            z0 = fmaf(P.b1, xvv, z1); z0 = fmaf(P.na1, yv, z0);
            z1 = fmaf(P.b2, xvv, z2); z1 = fmaf(P.na2, yv, z1);
            z2 = fmaf(P.b3, xvv, z3); z2 = fmaf(P.na3, yv, z2);
            z3 = P.b4 * xvv;          z3 = fmaf(P.na4, yv, z3);
            ov.z = yv; }
        {   float xvv = xv.w;
            float yv = fmaf(P.b0, xvv, z0);
            z0 = fmaf(P.b1, xvv, z1); z0 = fmaf(P.na1, yv, z0);
            z1 = fmaf(P.b2, xvv, z2); z1 = fmaf(P.na2, yv, z1);
            z2 = fmaf(P.b3, xvv, z3); z2 = fmaf(P.na3, yv, z2);
            z3 = P.b4 * xvv;          z3 = fmaf(P.na4, yv, z3);
            ov.w = yv; }
        *ap = ov;
    }
    __syncthreads();

    // ---- output: swizzled LDS.128 -> coalesced STG.128 ----
    float4* yout = reinterpret_cast<float4*>(y + gbase);
#pragma unroll
    for (int i = 0; i < REGION / (4 * CPB); i++) {
        int vidx = i * CPB + t;
        int c = vidx >> 4;
        int j = (vidx & 15) * 4;
        yout[vidx] = *reinterpret_cast<const float4*>(&sm[sidx4(c, j)]);
    }
}

// ---------------- host ----------------

struct Cd { double re, im; };
static inline Cd cadd(Cd a, Cd b) { return { a.re + b.re, a.im + b.im }; }
static inline Cd csub(Cd a, Cd b) { return { a.re - b.re, a.im - b.im }; }
static inline Cd cmul(Cd a, Cd b) {
    return { a.re * b.re - a.im * b.im, a.re * b.im + a.im * b.re };
}
static inline Cd cdiv(Cd a, Cd b) {
    double d = b.re * b.re + b.im * b.im;
    return { (a.re * b.re + a.im * b.im) / d, (a.im * b.re - a.re * b.im) / d };
}

extern "C" void kernel_launch(void* const* d_in, const int* in_sizes, int n_in,
                              void* d_out, int out_size) {
    const float* x = (const float*)d_in[0];
    float* y = (float*)d_out;

    // ---- Butterworth design, exactly mirroring the reference numpy math ----
    const int ORDER = 4;
    const double WN = 4000.0 / (0.5 * 16000.0);   // 0.5
    const double fs2 = 4.0;
    double warped = fs2 * tan(M_PI * WN / 4.0);

    Cd p[4];
    for (int k = 1; k <= ORDER; k++) {
        double ang = M_PI * (2 * k + ORDER - 1) / (2.0 * ORDER);
        p[k - 1] = { warped * cos(ang), warped * sin(ang) };
    }
    double gain = warped * warped * warped * warped;

    Cd pd[4];
    Cd prodden = { 1.0, 0.0 };
    for (int i = 0; i < 4; i++) {
        Cd num = cadd({ fs2, 0.0 }, p[i]);
        Cd den = csub({ fs2, 0.0 }, p[i]);
        pd[i] = cdiv(num, den);
        prodden = cmul(prodden, den);
    }
    double kd = gain / prodden.re;
    double bcoef[5] = { kd, 4.0 * kd, 6.0 * kd, 4.0 * kd, kd };

    Cd ac[5] = { {1,0}, {0,0}, {0,0}, {0,0}, {0,0} };
    for (int i = 0; i < 4; i++)
        for (int j = 4; j >= 1; j--)
            ac[j] = csub(ac[j], cmul(pd[i], ac[j - 1]));
    double acoef[5];
    for (int i = 0; i < 5; i++) acoef[i] = ac[i].re;

    // state transition: z' = A z + g x  (DF2T with y eliminated)
    double A[16] = {0};
    for (int i = 0; i < 4; i++) {
        A[i * 4 + 0] -= acoef[i + 1];
        if (i < 3) A[i * 4 + (i + 1)] += 1.0;
    }
    double g[4];
    for (int i = 0; i < 4; i++) g[i] = bcoef[i + 1] - acoef[i + 1] * bcoef[0];

    Params P;
    P.b0 = (float)bcoef[0]; P.b1 = (float)bcoef[1]; P.b2 = (float)bcoef[2];
    P.b3 = (float)bcoef[3]; P.b4 = (float)bcoef[4];
    P.na1 = (float)(-acoef[1]); P.na2 = (float)(-acoef[2]);
    P.na3 = (float)(-acoef[3]); P.na4 = (float)(-acoef[4]);

    // warmup weights: w_j = A^(W-1-j) g  (oldest sample gets highest power)
    double wv[4] = { g[0], g[1], g[2], g[3] };
    for (int j = W_WARM - 1; j >= 0; j--) {
        P.wq4[j] = make_float4((float)wv[0], (float)wv[1],
                               (float)wv[2], (float)wv[3]);
        double nv[4];
        for (int i = 0; i < 4; i++) {
            nv[i] = 0.0;
            for (int k2 = 0; k2 < 4; k2++) nv[i] += A[i * 4 + k2] * wv[k2];
        }
        for (int i = 0; i < 4; i++) wv[i] = nv[i];
    }

    fused_kernel<<<NBLK, CPB>>>(x, y, P);
}

// round 10
// speedup vs baseline: 2.7778x; 1.0875x over previous
#include <cuda_runtime.h>
#include <math.h>

#ifndef M_PI
#define M_PI 3.14159265358979323846
#endif

#define BATCH      256
#define T_LEN      65536
#define L_CHUNK    32
#define W_WARM     40                      // |p|^40/(1-|p|) ~ 6e-5
#define CPB        128                     // chunks (= threads) per block
#define REGION     (CPB * L_CHUNK)         // 4096 floats = 16KB
#define RB_PER_ROW (T_LEN / REGION)        // 16 blocks per batch row
#define NBLK       (BATCH * RB_PER_ROW)    // 4096 blocks

struct Params {
    float b0, b1, b2, b3, b4;      // numerator
    float na1, na2, na3, na4;      // negated denominator taps
    float4 wq4[W_WARM];            // warmup weights w_j = A^(W-1-j) g (const space)
};

// 16B-granule swizzle: word (chunk c, sample j) -> c*32 + (j ^ ((c&7)<<2)).
// XOR touches only bits 2..4 (j<32), aligned float4 groups stay contiguous,
// and every phase of every 128-bit smem op below is bank-conflict-free.
__device__ __forceinline__ int sidx4(int c, int j) {
    return c * L_CHUNK + (j ^ ((c & 7) << 2));
}

__device__ __forceinline__ void cpa16(unsigned dst_smem, const void* src) {
    asm volatile("cp.async.cg.shared.global [%0], [%1], 16;\n"
                 :: "r"(dst_smem), "l"(src));
}

__global__ void __launch_bounds__(CPB, 8) fused_kernel(const float* __restrict__ x,
                                                       float* __restrict__ y,
                                                       Params P) {
    __shared__ float4 smv[REGION / 4];
    __shared__ float4 padx4[W_WARM / 4];   // 40 floats: x[block_start-40 .. -1]
    float* sm = reinterpret_cast<float*>(smv);

    const int t   = threadIdx.x;
    const int blk = blockIdx.x;
    const int rb  = blk & (RB_PER_ROW - 1);
    const size_t gbase = (size_t)(blk >> 4) * T_LEN + (size_t)rb * REGION;

    // ---- stage: coalesced 16B cp.async -> swizzled smem ----
    const float4* xin = reinterpret_cast<const float4*>(x + gbase);
    unsigned smb = (unsigned)__cvta_generic_to_shared(sm);
#pragma unroll
    for (int i = 0; i < REGION / (4 * CPB); i++) {   // 8 iters
        int vidx = i * CPB + t;
        int c = vidx >> 3;                // 8 float4 per chunk
        int j = (vidx & 7) * 4;
        cpa16(smb + sidx4(c, j) * 4u, xin + vidx);
    }
    if (t < W_WARM / 4) {
        float4 d = make_float4(0.f, 0.f, 0.f, 0.f);
        if (rb != 0)
            d = reinterpret_cast<const float4*>(x + gbase - W_WARM)[t];
        padx4[t] = d;
    }
    asm volatile("cp.async.commit_group;\n");
    asm volatile("cp.async.wait_group 0;\n");
    __syncthreads();

    // ---- warmup: state = sum over previous 40 samples, w_j = A^(39-j) g ----
    // Window [-40,-1] rel. chunk start: q<2 -> chunk t-2 @ {24,28};
    // q>=2 -> chunk t-1 @ 4(q-2). Chunks <0 fall back to padx (zeros at row
    // start, which reproduces the zero-initial-condition state exactly).
    float z0 = 0.f, z1 = 0.f, z2 = 0.f, z3 = 0.f;
#pragma unroll
    for (int q = 0; q < W_WARM / 4; q++) {
        const int cc  = (q < 2) ? (t - 2) : (t - 1);
        const int off = (q < 2) ? (24 + 4 * q) : (4 * (q - 2));
        const float4* p = (cc >= 0)
            ? reinterpret_cast<const float4*>(&sm[sidx4(cc, off)])
            : &padx4[8 * t + q];       // padx word index = 32t + 4q
        float4 xv = *p;
        float4 w0 = P.wq4[4 * q + 0], w1 = P.wq4[4 * q + 1];
        float4 w2 = P.wq4[4 * q + 2], w3 = P.wq4[4 * q + 3];
        z0 = fmaf(w0.x, xv.x, z0); z1 = fmaf(w0.y, xv.x, z1);
        z2 = fmaf(w0.z, xv.x, z2); z3 = fmaf(w0.w, xv.x, z3);
        z0 = fmaf(w1.x, xv.y, z0); z1 = fmaf(w1.y, xv.y, z1);
        z2 = fmaf(w1.z, xv.y, z2); z3 = fmaf(w1.w, xv.y, z3);
        z0 = fmaf(w2.x, xv.z, z0); z1 = fmaf(w2.y, xv.z, z1);
        z2 = fmaf(w2.z, xv.z, z2); z3 = fmaf(w2.w, xv.z, z3);
        z0 = fmaf(w3.x, xv.w, z0); z1 = fmaf(w3.y, xv.w, z1);
        z2 = fmaf(w3.z, xv.w, z2); z3 = fmaf(w3.w, xv.w, z3);
    }
    __syncthreads();   // all warmup reads done before in-place overwrite

    // ---- main: DF2T over own chunk (vectorized smem IO), y in place ----
#pragma unroll
    for (int q = 0; q < L_CHUNK / 4; q++) {
        float4* ap = reinterpret_cast<float4*>(&sm[sidx4(t, 4 * q)]);
        float4 xv = *ap;
        float4 ov;
        {   float xvv = xv.x;
            float yv = fmaf(P.b0, xvv, z0);
            z0 = fmaf(P.b1, xvv, z1); z0 = fmaf(P.na1, yv, z0);
            z1 = fmaf(P.b2, xvv, z2); z1 = fmaf(P.na2, yv, z1);
            z2 = fmaf(P.b3, xvv, z3); z2 = fmaf(P.na3, yv, z2);
            z3 = P.b4 * xvv;          z3 = fmaf(P.na4, yv, z3);
            ov.x = yv; }
        {   float xvv = xv.y;
            float yv = fmaf(P.b0, xvv, z0);
            z0 = fmaf(P.b1, xvv, z1); z0 = fmaf(P.na1, yv, z0);
            z1 = fmaf(P.b2, xvv, z2); z1 = fmaf(P.na2, yv, z1);
            z2 = fmaf(P.b3, xvv, z3); z2 = fmaf(P.na3, yv, z2);
            z3 = P.b4 * xvv;          z3 = fmaf(P.na4, yv, z3);
            ov.y = yv; }
        {   float xvv = xv.z;
            float yv = fmaf(P.b0, xvv, z0);
            z0 = fmaf(P.b1, xvv, z1); z0 = fmaf(P.na1, yv, z0);
            z1 = fmaf(P.b2, xvv, z2); z1 = fmaf(P.na2, yv, z1);
            z2 = fmaf(P.b3, xvv, z3); z2 = fmaf(P.na3, yv, z2);
            z3 = P.b4 * xvv;          z3 = fmaf(P.na4, yv, z3);
            ov.z = yv; }
        {   float xvv = xv.w;
            float yv = fmaf(P.b0, xvv, z0);
            z0 = fmaf(P.b1, xvv, z1); z0 = fmaf(P.na1, yv, z0);
            z1 = fmaf(P.b2, xvv, z2); z1 = fmaf(P.na2, yv, z1);
            z2 = fmaf(P.b3, xvv, z3); z2 = fmaf(P.na3, yv, z2);
            z3 = P.b4 * xvv;          z3 = fmaf(P.na4, yv, z3);
            ov.w = yv; }
        *ap = ov;
    }
    __syncthreads();

    // ---- output: swizzled LDS.128 -> coalesced STG.128 ----
    float4* yout = reinterpret_cast<float4*>(y + gbase);
#pragma unroll
    for (int i = 0; i < REGION / (4 * CPB); i++) {
        int vidx = i * CPB + t;
        int c = vidx >> 3;
        int j = (vidx & 7) * 4;
        yout[vidx] = *reinterpret_cast<const float4*>(&sm[sidx4(c, j)]);
    }
}

// ---------------- host ----------------

struct Cd { double re, im; };
static inline Cd cadd(Cd a, Cd b) { return { a.re + b.re, a.im + b.im }; }
static inline Cd csub(Cd a, Cd b) { return { a.re - b.re, a.im - b.im }; }
static inline Cd cmul(Cd a, Cd b) {
    return { a.re * b.re - a.im * b.im, a.re * b.im + a.im * b.re };
}
static inline Cd cdiv(Cd a, Cd b) {
    double d = b.re * b.re + b.im * b.im;
    return { (a.re * b.re + a.im * b.im) / d, (a.im * b.re - a.re * b.im) / d };
}

extern "C" void kernel_launch(void* const* d_in, const int* in_sizes, int n_in,
                              void* d_out, int out_size) {
    const float* x = (const float*)d_in[0];
    float* y = (float*)d_out;

    // ---- Butterworth design, exactly mirroring the reference numpy math ----
    const int ORDER = 4;
    const double WN = 4000.0 / (0.5 * 16000.0);   // 0.5
    const double fs2 = 4.0;
    double warped = fs2 * tan(M_PI * WN / 4.0);

    Cd p[4];
    for (int k = 1; k <= ORDER; k++) {
        double ang = M_PI * (2 * k + ORDER - 1) / (2.0 * ORDER);
        p[k - 1] = { warped * cos(ang), warped * sin(ang) };
    }
    double gain = warped * warped * warped * warped;

    Cd pd[4];
    Cd prodden = { 1.0, 0.0 };
    for (int i = 0; i < 4; i++) {
        Cd num = cadd({ fs2, 0.0 }, p[i]);
        Cd den = csub({ fs2, 0.0 }, p[i]);
        pd[i] = cdiv(num, den);
        prodden = cmul(prodden, den);
    }
    double kd = gain / prodden.re;
    double bcoef[5] = { kd, 4.0 * kd, 6.0 * kd, 4.0 * kd, kd };

    Cd ac[5] = { {1,0}, {0,0}, {0,0}, {0,0}, {0,0} };
    for (int i = 0; i < 4; i++)
        for (int j = 4; j >= 1; j--)
            ac[j] = csub(ac[j], cmul(pd[i], ac[j - 1]));
    double acoef[5];
    for (int i = 0; i < 5; i++) acoef[i] = ac[i].re;

    // state transition: z' = A z + g x  (DF2T with y eliminated)
    double A[16] = {0};
    for (int i = 0; i < 4; i++) {
        A[i * 4 + 0] -= acoef[i + 1];
        if (i < 3) A[i * 4 + (i + 1)] += 1.0;
    }
    double g[4];
    for (int i = 0; i < 4; i++) g[i] = bcoef[i + 1] - acoef[i + 1] * bcoef[0];

    Params P;
    P.b0 = (float)bcoef[0]; P.b1 = (float)bcoef[1]; P.b2 = (float)bcoef[2];
    P.b3 = (float)bcoef[3]; P.b4 = (float)bcoef[4];
    P.na1 = (float)(-acoef[1]); P.na2 = (float)(-acoef[2]);
    P.na3 = (float)(-acoef[3]); P.na4 = (float)(-acoef[4]);

    // warmup weights: w_j = A^(W-1-j) g  (oldest sample gets highest power)
    double wv[4] = { g[0], g[1], g[2], g[3] };
    for (int j = W_WARM - 1; j >= 0; j--) {
        P.wq4[j] = make_float4((float)wv[0], (float)wv[1],
                               (float)wv[2], (float)wv[3]);
        double nv[4];
        for (int i = 0; i < 4; i++) {
            nv[i] = 0.0;
            for (int k2 = 0; k2 < 4; k2++) nv[i] += A[i * 4 + k2] * wv[k2];
        }
        for (int i = 0; i < 4; i++) wv[i] = nv[i];
    }

    fused_kernel<<<NBLK, CPB>>>(x, y, P);
}